// round 16
// baseline (speedup 1.0000x reference)
#include <cuda_runtime.h>

// out = cumprod_j( cos(w_j) * cos(x @ W_pre^T + b_pre) ) @ W_post^T + b_post
//
// Analytic reduction of the quantum layer:
//   z_j   = cos(q_weights_j) * cos(angle_j)
//   <Z_i> = prod_{j<=i} z_j            (CNOT chain = prefix-XOR)
//
// Block = (row pair, column half): grid=256 x 512 thr, 2 blocks/SM.
// SPLIT-K-2 phase 1 (best measured body, R14): warp w handles qubit pair
// {2(w&7), 2(w&7)+1} over K-half (w>>3). Dual-row fold reduction: 10
// shuffles instead of 20. Partials combined through 256 B smem in phase 2.
// One block barrier total.

#define NQ   16
#define DIN  1024
#define DOUT 1024
#define B    256

__global__ __launch_bounds__(512, 2)
void quantum_projector_kernel(const float* __restrict__ x,
                              const float* __restrict__ W_pre,
                              const float* __restrict__ b_pre,
                              const float* __restrict__ q_weights,
                              const float* __restrict__ W_post,
                              const float* __restrict__ b_post,
                              float* __restrict__ out)
{
    __shared__ float  s_part[2][2][NQ];  // [K-half][row][qubit] partial dots
    __shared__ float4 s_wz[16][8];       // warp-private scan slots

    const int bx   = blockIdx.x;
    const int pair = bx >> 1;            // which row pair
    const int half = bx & 1;             // which 512-column half
    const int r0   = pair * 2;
    const int r1   = r0 + 1;
    const int tid  = threadIdx.x;
    const int warp = tid >> 5;
    const int lane = tid & 31;

    // ---- Prefetch this thread's W_post column (shared by both rows) ----
    const int col = half * 512 + tid;
    const float4* __restrict__ Wp4 = reinterpret_cast<const float4*>(W_post);
    float4 wreg[4];
#pragma unroll
    for (int i = 0; i < 4; i++)
        wreg[i] = Wp4[col * 4 + i];
    const float bp = b_post[col];

    // ---- Phase 1 (split-K-2): warp w -> qubits {2qp, 2qp+1}, K-half kh ----
    {
        const int kh = warp >> 3;            // 0: K[0,512), 1: K[512,1024)
        const int qp = warp & 7;
        const int q0 = qp * 2, q1 = q0 + 1;
        const int kbase = kh * 128;          // float4 offset of this K-half

        const float4* __restrict__ wa4 = reinterpret_cast<const float4*>(W_pre + q0 * DIN) + kbase;
        const float4* __restrict__ wb4 = reinterpret_cast<const float4*>(W_pre + q1 * DIN) + kbase;
        const float4* __restrict__ x04 = reinterpret_cast<const float4*>(x + r0 * DIN) + kbase;
        const float4* __restrict__ x14 = reinterpret_cast<const float4*>(x + r1 * DIN) + kbase;

        float a00 = 0.f, a01 = 0.f, a10 = 0.f, a11 = 0.f;   // [row][qubit]
#pragma unroll
        for (int i = 0; i < 4; i++) {
            const int k = lane + 32 * i;     // 128 float4 per K-half, 4/lane
            const float4 wa = wa4[k];
            const float4 wb = wb4[k];
            const float4 x0 = x04[k];
            const float4 x1 = x14[k];
            a00 += x0.x * wa.x + x0.y * wa.y + x0.z * wa.z + x0.w * wa.w;
            a01 += x0.x * wb.x + x0.y * wb.y + x0.z * wb.z + x0.w * wb.w;
            a10 += x1.x * wa.x + x1.y * wa.y + x1.z * wa.z + x1.w * wa.w;
            a11 += x1.x * wb.x + x1.y * wb.y + x1.z * wb.z + x1.w * wb.w;
        }

        // Dual-row fold: xor16 all four, lanes<16 carry row0's two qubits,
        // lanes>=16 carry row1's; then xor8..1 on just 2 values (10 shuffles).
        a00 += __shfl_xor_sync(0xffffffffu, a00, 16);
        a01 += __shfl_xor_sync(0xffffffffu, a01, 16);
        a10 += __shfl_xor_sync(0xffffffffu, a10, 16);
        a11 += __shfl_xor_sync(0xffffffffu, a11, 16);
        float v0 = (lane < 16) ? a00 : a10;  // qubit q0, row (lane>=16)
        float v1 = (lane < 16) ? a01 : a11;  // qubit q1
#pragma unroll
        for (int off = 8; off >= 1; off >>= 1) {
            v0 += __shfl_xor_sync(0xffffffffu, v0, off);
            v1 += __shfl_xor_sync(0xffffffffu, v1, off);
        }
        if (lane == 0) {
            s_part[kh][0][q0] = v0;
            s_part[kh][0][q1] = v1;
        }
        if (lane == 16) {
            s_part[kh][1][q0] = v0;
            s_part[kh][1][q1] = v1;
        }
    }
    __syncthreads();   // the ONLY block barrier: partials ready

    // ---- Phase 2: EVERY warp combines partials + dual-row prefix scan ----
    // lanes 0..15 -> row0, lanes 16..31 -> row1 (segmented shfl_up scan),
    // broadcast within the warp via its private smem slot.
    {
        const int q   = lane & 15;
        const int seg = lane >> 4;
        const float angle = s_part[0][seg][q] + s_part[1][seg][q] + b_pre[q];
        float v = __cosf(q_weights[q]) * __cosf(angle);
#pragma unroll
        for (int off = 1; off <= 8; off <<= 1) {
            float t = __shfl_up_sync(0xffffffffu, v, off);
            if (q >= off) v *= t;   // segment boundary: q < off blocks carry-in
        }
        reinterpret_cast<float*>(s_wz[warp])[lane] = v;
        __syncwarp();
    }

    // ---- Phase 3: one column x 2 rows per thread; zq via broadcast LDS.128 ----
    float d0 = bp, d1 = bp;
#pragma unroll
    for (int i = 0; i < 4; i++) {
        const float4 za = s_wz[warp][i];       // row0 qubits 4i..4i+3
        const float4 zb = s_wz[warp][4 + i];   // row1
        const float4 w  = wreg[i];
        d0 += za.x * w.x + za.y * w.y + za.z * w.z + za.w * w.w;
        d1 += zb.x * w.x + zb.y * w.y + zb.z * w.z + zb.w * w.w;
    }

    out[r0 * DOUT + col] = d0;
    out[r1 * DOUT + col] = d1;
}

extern "C" void kernel_launch(void* const* d_in, const int* in_sizes, int n_in,
                              void* d_out, int out_size)
{
    const float* x         = (const float*)d_in[0];   // [256, 1024]
    const float* W_pre     = (const float*)d_in[1];   // [16, 1024]
    const float* b_pre     = (const float*)d_in[2];   // [16]
    const float* q_weights = (const float*)d_in[3];   // [16]
    const float* W_post    = (const float*)d_in[4];   // [1024, 16]
    const float* b_post    = (const float*)d_in[5];   // [1024]
    float* out             = (float*)d_out;           // [256, 1024]

    quantum_projector_kernel<<<B, 512>>>(x, W_pre, b_pre, q_weights,
                                         W_post, b_post, out);
}

// round 17
// speedup vs baseline: 1.1674x; 1.1674x over previous
#include <cuda_runtime.h>

// out = cumprod_j( cos(w_j) * cos(x @ W_pre^T + b_pre) ) @ W_post^T + b_post
//
// Analytic reduction of the quantum layer:
//   z_j   = cos(q_weights_j) * cos(angle_j)
//   <Z_i> = prod_{j<=i} z_j            (CNOT chain = prefix-XOR)
//
// ONE block per row pair: grid=128 x 1024 thr, 1 block/SM, occ 50%.
// Phase-1 redundancy eliminated (previously duplicated across two
// column-half blocks): per-SM crossbar traffic drops ~40%.
//   - phase 1: split-K-4 x qubit-pair across all 32 warps
//     (warp w -> qubits {2(w&7), 2(w&7)+1}, K-quarter w>>3)
//   - dual-row fold reduction (10 shuffles)
//   - per-warp redundant segmented prefix scan + __syncwarp broadcast
//   - phase 3: one column x 2 rows per thread, W_post register-cached
//   - one block barrier total

#define NQ   16
#define DIN  1024
#define DOUT 1024

__global__ __launch_bounds__(1024, 1)
void quantum_projector_kernel(const float* __restrict__ x,
                              const float* __restrict__ W_pre,
                              const float* __restrict__ b_pre,
                              const float* __restrict__ q_weights,
                              const float* __restrict__ W_post,
                              const float* __restrict__ b_post,
                              float* __restrict__ out)
{
    __shared__ float  s_part[4][2][NQ];  // [K-quarter][row][qubit] partial dots
    __shared__ float4 s_wz[32][8];       // warp-private scan slots

    const int pair = blockIdx.x;
    const int r0   = pair * 2;
    const int r1   = r0 + 1;
    const int tid  = threadIdx.x;
    const int warp = tid >> 5;           // 32 warps
    const int lane = tid & 31;

    // ---- Prefetch this thread's W_post column (shared by both rows) ----
    const int col = tid;                 // 1024 columns, one per thread
    const float4* __restrict__ Wp4 = reinterpret_cast<const float4*>(W_post);
    float4 wreg[4];
#pragma unroll
    for (int i = 0; i < 4; i++)
        wreg[i] = Wp4[col * 4 + i];
    const float bp = b_post[col];

    // ---- Phase 1: warp w -> qubits {2qp, 2qp+1}, K-quarter kq ----
    {
        const int qp = warp & 7;
        const int kq = warp >> 3;            // K-quarter 0..3
        const int q0 = qp * 2, q1 = q0 + 1;
        const int kbase = kq * 64;           // float4 offset (256 floats/quarter)

        const float4* __restrict__ wa4 = reinterpret_cast<const float4*>(W_pre + q0 * DIN) + kbase;
        const float4* __restrict__ wb4 = reinterpret_cast<const float4*>(W_pre + q1 * DIN) + kbase;
        const float4* __restrict__ x04 = reinterpret_cast<const float4*>(x + r0 * DIN) + kbase;
        const float4* __restrict__ x14 = reinterpret_cast<const float4*>(x + r1 * DIN) + kbase;

        float a00 = 0.f, a01 = 0.f, a10 = 0.f, a11 = 0.f;   // [row][qubit]
#pragma unroll
        for (int i = 0; i < 2; i++) {
            const int k = lane + 32 * i;     // 64 float4 per quarter, 2/lane
            const float4 wa = wa4[k];
            const float4 wb = wb4[k];
            const float4 x0 = x04[k];
            const float4 x1 = x14[k];
            a00 += x0.x * wa.x + x0.y * wa.y + x0.z * wa.z + x0.w * wa.w;
            a01 += x0.x * wb.x + x0.y * wb.y + x0.z * wb.z + x0.w * wb.w;
            a10 += x1.x * wa.x + x1.y * wa.y + x1.z * wa.z + x1.w * wa.w;
            a11 += x1.x * wb.x + x1.y * wb.y + x1.z * wb.z + x1.w * wb.w;
        }

        // Dual-row fold: xor16 all four, lanes<16 carry row0's two qubits,
        // lanes>=16 carry row1's; then xor8..1 on 2 values (10 shuffles).
        a00 += __shfl_xor_sync(0xffffffffu, a00, 16);
        a01 += __shfl_xor_sync(0xffffffffu, a01, 16);
        a10 += __shfl_xor_sync(0xffffffffu, a10, 16);
        a11 += __shfl_xor_sync(0xffffffffu, a11, 16);
        float v0 = (lane < 16) ? a00 : a10;
        float v1 = (lane < 16) ? a01 : a11;
#pragma unroll
        for (int off = 8; off >= 1; off >>= 1) {
            v0 += __shfl_xor_sync(0xffffffffu, v0, off);
            v1 += __shfl_xor_sync(0xffffffffu, v1, off);
        }
        if (lane == 0) {
            s_part[kq][0][q0] = v0;
            s_part[kq][0][q1] = v1;
        }
        if (lane == 16) {
            s_part[kq][1][q0] = v0;
            s_part[kq][1][q1] = v1;
        }
    }
    __syncthreads();   // the ONLY block barrier: partials ready

    // ---- Phase 2: EVERY warp combines partials + dual-row prefix scan ----
    // lanes 0..15 -> row0, lanes 16..31 -> row1 (segmented shfl_up scan),
    // broadcast within the warp via its private smem slot.
    {
        const int q   = lane & 15;
        const int seg = lane >> 4;
        const float angle = s_part[0][seg][q] + s_part[1][seg][q]
                          + s_part[2][seg][q] + s_part[3][seg][q] + b_pre[q];
        float v = __cosf(q_weights[q]) * __cosf(angle);
#pragma unroll
        for (int off = 1; off <= 8; off <<= 1) {
            float t = __shfl_up_sync(0xffffffffu, v, off);
            if (q >= off) v *= t;   // segment boundary: q < off blocks carry-in
        }
        reinterpret_cast<float*>(s_wz[warp])[lane] = v;
        __syncwarp();
    }

    // ---- Phase 3: one column x 2 rows per thread; zq via broadcast LDS.128 ----
    float d0 = bp, d1 = bp;
#pragma unroll
    for (int i = 0; i < 4; i++) {
        const float4 za = s_wz[warp][i];       // row0 qubits 4i..4i+3
        const float4 zb = s_wz[warp][4 + i];   // row1
        const float4 w  = wreg[i];
        d0 += za.x * w.x + za.y * w.y + za.z * w.z + za.w * w.w;
        d1 += zb.x * w.x + zb.y * w.y + zb.z * w.z + zb.w * w.w;
    }

    out[r0 * DOUT + col] = d0;
    out[r1 * DOUT + col] = d1;
}

extern "C" void kernel_launch(void* const* d_in, const int* in_sizes, int n_in,
                              void* d_out, int out_size)
{
    const float* x         = (const float*)d_in[0];   // [256, 1024]
    const float* W_pre     = (const float*)d_in[1];   // [16, 1024]
    const float* b_pre     = (const float*)d_in[2];   // [16]
    const float* q_weights = (const float*)d_in[3];   // [16]
    const float* W_post    = (const float*)d_in[4];   // [1024, 16]
    const float* b_post    = (const float*)d_in[5];   // [1024]
    float* out             = (float*)d_out;           // [256, 1024]

    quantum_projector_kernel<<<128, 1024>>>(x, W_pre, b_pre, q_weights,
                                            W_post, b_post, out);
}